// round 10
// baseline (speedup 1.0000x reference)
#include <cuda_runtime.h>
#include <math.h>
#include <stdint.h>

#define NN 12288
#define EE 196608
#define FIN 1433

// ---------------- scratch (no allocations allowed) ----------------
__device__ __align__(16) float g_xw[NN * 32];    // x @ W1 (atomic accum)
__device__ __align__(16) float g_h[NN * 32];     // GCN output (post relu)
__device__ int   g_deg[NN];       // in-degree over col (excl self loop)
__device__ int   g_cnt[NN];       // out-degree over src
__device__ float g_dis[NN];       // (deg+1)^-1/2
__device__ int   g_is64;
__device__ int   g_src[EE];       // int32 edge cache
__device__ int   g_dst[EE];
__device__ int   g_rank[EE];      // edge's rank within its src bucket
__device__ int   g_ptr[NN + 1];   // CSR row pointers (by src)
__device__ int   g_csr[EE];       // CSR column (dst) list

__device__ __forceinline__ int edge_at(const void* ei, int j) {
    if (g_is64) return (int)((const long long*)ei)[j];
    return ((const int*)ei)[j];
}

// f32x2 packed FMA helpers
__device__ __forceinline__ void ffma2(unsigned long long& d,
                                      unsigned long long a,
                                      unsigned long long b) {
    asm("fma.rn.f32x2 %0, %1, %2, %0;" : "+l"(d) : "l"(a), "l"(b));
}
__device__ __forceinline__ unsigned long long dup2(float v) {
    unsigned long long r;
    asm("mov.b64 %0, {%1, %1};" : "=l"(r) : "f"(v));
    return r;
}
__device__ __forceinline__ float2 unpack2(unsigned long long v) {
    float2 r;
    asm("mov.b64 {%0, %1}, %2;" : "=f"(r.x), "=f"(r.y) : "l"(v));
    return r;
}
// cp.async 4B with zero-fill when pred is false
__device__ __forceinline__ void cp4(uint32_t dst_smem, const float* src, bool pred) {
    int sz = pred ? 4 : 0;
    asm volatile("cp.async.ca.shared.global [%0], [%1], 4, %2;"
                 :: "r"(dst_smem), "l"(src), "r"(sz));
}

// ---------------- K0a: zero g_xw (GEMM chain) ----------------
__global__ void k_zero_xw() {
    int t = blockIdx.x * blockDim.x + threadIdx.x;
    if (t < NN * 32) g_xw[t] = 0.f;
}

// ---------------- K0b: zero deg/cnt + dtype detect (edge chain) -------------
__global__ void k_zero_edge(const int* __restrict__ ei32) {
    int t = blockIdx.x * blockDim.x + threadIdx.x;
    if (t < NN) { g_deg[t] = 0; g_cnt[t] = 0; }
    if (t == 0) {
        int all_zero_high = 1;
        for (int i = 0; i < 64; i++)
            if (ei32[2 * i + 1] != 0) { all_zero_high = 0; break; }
        g_is64 = all_zero_high;
    }
}

// ---------------- K1: degrees + edge cache + src-bucket rank ----------------
__global__ void k_deg(const void* __restrict__ ei) {
    int e = blockIdx.x * blockDim.x + threadIdx.x;
    if (e >= EE) return;
    int s = edge_at(ei, e);
    int c = edge_at(ei, EE + e);
    g_src[e] = s;
    g_dst[e] = c;
    atomicAdd(&g_deg[c], 1);
    g_rank[e] = atomicAdd(&g_cnt[s], 1);
}

// ---------------- K2: block scan of cnt -> ptr, plus dis ----------------
__global__ __launch_bounds__(1024) void k_scan() {
    __shared__ int warp_tot[32];
    int tid = threadIdx.x;
    int lane = tid & 31, wid = tid >> 5;
    int base = tid * 12;
    int loc[12];
    int s = 0;
#pragma unroll
    for (int i = 0; i < 12; i++) { loc[i] = g_cnt[base + i]; s += loc[i]; }
    int t = s;
#pragma unroll
    for (int off = 1; off < 32; off <<= 1) {
        int v = __shfl_up_sync(0xffffffffu, t, off);
        if (lane >= off) t += v;
    }
    if (lane == 31) warp_tot[wid] = t;
    __syncthreads();
    if (wid == 0) {
        int v = warp_tot[lane];
        int tv = v;
#pragma unroll
        for (int off = 1; off < 32; off <<= 1) {
            int u = __shfl_up_sync(0xffffffffu, tv, off);
            if (lane >= off) tv += u;
        }
        warp_tot[lane] = tv - v;  // exclusive warp base
    }
    __syncthreads();
    int run = warp_tot[wid] + (t - s);
#pragma unroll
    for (int i = 0; i < 12; i++) {
        g_ptr[base + i] = run;
        run += loc[i];
    }
    if (tid == 1023) g_ptr[NN] = run;
    for (int i = tid; i < NN; i += 1024)
        g_dis[i] = 1.0f / sqrtf((float)(g_deg[i] + 1));
}

// ---------------- K3: CSR placement (no atomics) ----------------
__global__ void k_place() {
    int e = blockIdx.x * blockDim.x + threadIdx.x;
    if (e >= EE) return;
    int s = g_src[e];
    g_csr[g_ptr[s] + g_rank[e]] = g_dst[e];
}

// ---------------- K4: xw += x @ W1, f32x2 FMA, cp.async, 4-way K split -----
#define BM 32
#define BK 32
#define KSPLIT 4
__global__ __launch_bounds__(64) void k_gemm(const float* __restrict__ x,
                                             const float* __restrict__ W1) {
    __shared__ float xs[2][BK][BM + 4];
    __shared__ float ws[2][BK][32];
    const int tid = threadIdx.x;
    const int tx = tid & 7;
    const int ty = tid >> 3;
    const int row0 = blockIdx.x * BM;
    const int lk = tid & 31;
    const int lr = tid >> 5;
    // 45 tiles split 12/11/11/11 across blockIdx.y
    const int y = blockIdx.y;
    const int t0 = (y == 0) ? 0 : (1 + y * 11);
    const int t1 = t0 + ((y == 0) ? 12 : 11);

    unsigned long long acc[4][2];
#pragma unroll
    for (int r = 0; r < 4; r++)
#pragma unroll
        for (int c = 0; c < 2; c++) acc[r][c] = 0ULL;

    auto copy_tile = [&](int t, int b) {
        int k0 = t * BK;
        int k = k0 + lk;
        bool kin = (k < FIN);
        const float* xp = kin ? &x[(row0 + lr) * FIN + k] : x;
#pragma unroll
        for (int i = 0; i < 16; i++) {
            int r = lr + i * 2;
            uint32_t dst = (uint32_t)__cvta_generic_to_shared(&xs[b][lk][r]);
            cp4(dst, kin ? &x[(row0 + r) * FIN + k] : xp, kin);
        }
#pragma unroll
        for (int i = 0; i < 16; i++) {
            int idx = tid + i * 64;
            int kk = idx >> 5, c = idx & 31;
            bool win = (k0 + kk) < FIN;
            uint32_t dst = (uint32_t)__cvta_generic_to_shared(&ws[b][kk][c]);
            cp4(dst, win ? &W1[(k0 + kk) * 32 + c] : W1, win);
        }
        asm volatile("cp.async.commit_group;" ::: "memory");
    };

    copy_tile(t0, 0);
    for (int t = t0; t < t1; t++) {
        int b = (t - t0) & 1;
        bool has_next = (t + 1 < t1);
        if (has_next) copy_tile(t + 1, b ^ 1);
        if (has_next)
            asm volatile("cp.async.wait_group 1;" ::: "memory");
        else
            asm volatile("cp.async.wait_group 0;" ::: "memory");
        __syncthreads();
#pragma unroll
        for (int kk = 0; kk < BK; kk++) {
            float4 a = *reinterpret_cast<const float4*>(&xs[b][kk][ty * 4]);
            ulonglong2 bb = *reinterpret_cast<const ulonglong2*>(&ws[b][kk][tx * 4]);
            unsigned long long a0 = dup2(a.x), a1 = dup2(a.y);
            unsigned long long a2 = dup2(a.z), a3 = dup2(a.w);
            ffma2(acc[0][0], a0, bb.x); ffma2(acc[0][1], a0, bb.y);
            ffma2(acc[1][0], a1, bb.x); ffma2(acc[1][1], a1, bb.y);
            ffma2(acc[2][0], a2, bb.x); ffma2(acc[2][1], a2, bb.y);
            ffma2(acc[3][0], a3, bb.x); ffma2(acc[3][1], a3, bb.y);
        }
        __syncthreads();
    }
#pragma unroll
    for (int r = 0; r < 4; r++) {
        float2 lo = unpack2(acc[r][0]);
        float2 hi = unpack2(acc[r][1]);
        float* dst = &g_xw[(row0 + ty * 4 + r) * 32 + tx * 4];
        atomicAdd(dst + 0, lo.x);
        atomicAdd(dst + 1, lo.y);
        atomicAdd(dst + 2, hi.x);
        atomicAdd(dst + 3, hi.y);
    }
}

// ---------------- K5: GCN gather, 8 threads/node, float4 -------------------
// thread group g (8 threads) handles node; each thread owns 4 features.
__global__ __launch_bounds__(256) void k_gcn(const float* __restrict__ b1) {
    int tid = threadIdx.x;
    int node = blockIdx.x * 32 + (tid >> 3);
    int q = (tid & 7) * 4;
    int p0 = g_ptr[node], p1 = g_ptr[node + 1];
    float4 acc = make_float4(0.f, 0.f, 0.f, 0.f);
    int j = p0;
    for (; j + 2 <= p1; j += 2) {
        int c0 = g_csr[j], c1 = g_csr[j + 1];
        float w0 = g_dis[c0], w1 = g_dis[c1];
        float4 v0 = *reinterpret_cast<const float4*>(&g_xw[c0 * 32 + q]);
        float4 v1 = *reinterpret_cast<const float4*>(&g_xw[c1 * 32 + q]);
        acc.x = fmaf(w0, v0.x, acc.x); acc.y = fmaf(w0, v0.y, acc.y);
        acc.z = fmaf(w0, v0.z, acc.z); acc.w = fmaf(w0, v0.w, acc.w);
        acc.x = fmaf(w1, v1.x, acc.x); acc.y = fmaf(w1, v1.y, acc.y);
        acc.z = fmaf(w1, v1.z, acc.z); acc.w = fmaf(w1, v1.w, acc.w);
    }
    if (j < p1) {
        int c = g_csr[j];
        float w = g_dis[c];
        float4 v = *reinterpret_cast<const float4*>(&g_xw[c * 32 + q]);
        acc.x = fmaf(w, v.x, acc.x); acc.y = fmaf(w, v.y, acc.y);
        acc.z = fmaf(w, v.z, acc.z); acc.w = fmaf(w, v.w, acc.w);
    }
    float di = g_dis[node];
    float d2 = di * di;
    float4 sv = *reinterpret_cast<const float4*>(&g_xw[node * 32 + q]);
    float4 bv = *reinterpret_cast<const float4*>(&b1[q]);
    float4 o;
    o.x = fmaxf(fmaf(di, acc.x, fmaf(d2, sv.x, bv.x)), 0.f);
    o.y = fmaxf(fmaf(di, acc.y, fmaf(d2, sv.y, bv.y)), 0.f);
    o.z = fmaxf(fmaf(di, acc.z, fmaf(d2, sv.z, bv.z)), 0.f);
    o.w = fmaxf(fmaf(di, acc.w, fmaf(d2, sv.w, bv.w)), 0.f);
    *reinterpret_cast<float4*>(&g_h[node * 32 + q]) = o;
}

// ---------------- K6: SAGE gather + normalize + head (fused) ---------------
__global__ __launch_bounds__(256) void k_sagehead(const float* __restrict__ Wl,
                                                  const float* __restrict__ bl,
                                                  const float* __restrict__ Wr,
                                                  const float* __restrict__ br,
                                                  const float* __restrict__ W3,
                                                  const float* __restrict__ b3,
                                                  float* __restrict__ out) {
    __shared__ float sWl[512], sWr[512], sW3[112], sbl[16], sbr[16], sb3[7];
    int tid = threadIdx.x;
    for (int i = tid; i < 512; i += 256) { sWl[i] = Wl[i]; sWr[i] = Wr[i]; }
    if (tid < 112) sW3[tid] = W3[tid];
    if (tid < 16) { sbl[tid] = bl[tid]; sbr[tid] = br[tid]; }
    if (tid < 7)  sb3[tid] = b3[tid];
    __syncthreads();

    const unsigned FULL = 0xffffffffu;
    int warp = (blockIdx.x * 256 + tid) >> 5;
    int lane = tid & 31;
    if (warp >= NN) return;
    int node = warp;

    int p0 = g_ptr[node], p1 = g_ptr[node + 1];
    float s = 0.f;
    int j = p0;
    for (; j + 4 <= p1; j += 4) {
        int c0 = g_csr[j], c1 = g_csr[j + 1];
        int c2 = g_csr[j + 2], c3 = g_csr[j + 3];
        s += g_h[c0 * 32 + lane] + g_h[c1 * 32 + lane]
           + g_h[c2 * 32 + lane] + g_h[c3 * 32 + lane];
    }
    for (; j < p1; j++) s += g_h[g_csr[j] * 32 + lane];
    int cnt = p1 - p0;
    float ak = (cnt > 0) ? s / (float)cnt : 0.f;
    float hk = g_h[node * 32 + lane];

    int l16 = lane & 15;
    float acc = 0.f;
#pragma unroll
    for (int k = 0; k < 32; k++) {
        float hv = __shfl_sync(FULL, hk, k);
        float av = __shfl_sync(FULL, ak, k);
        acc = fmaf(hv, sWl[k * 16 + l16], acc);
        acc = fmaf(av, sWr[k * 16 + l16], acc);
    }
    float o = fmaxf(acc + sbl[l16] + sbr[l16], 0.f);
    if (lane >= 16) o = 0.f;

    float ss = o * o;
#pragma unroll
    for (int off = 16; off; off >>= 1) ss += __shfl_xor_sync(FULL, ss, off);
    float on = o / (sqrtf(ss) + 1e-6f);

    int c7 = lane < 7 ? lane : 6;
    float lg = 0.f;
#pragma unroll
    for (int k = 0; k < 16; k++) {
        float ov = __shfl_sync(FULL, on, k);
        lg = fmaf(ov, sW3[k * 7 + c7], lg);
    }
    lg += sb3[c7];

    float v = lane < 7 ? lg : -INFINITY;
    float m = v;
#pragma unroll
    for (int off = 4; off; off >>= 1) m = fmaxf(m, __shfl_xor_sync(FULL, m, off));
    float ex = lane < 7 ? expf(lg - m) : 0.f;
    float sm = ex;
#pragma unroll
    for (int off = 4; off; off >>= 1) sm += __shfl_xor_sync(FULL, sm, off);
    if (lane < 7) out[node * 7 + lane] = ex / sm;
}

// ---------------- launch (forked capture: edge chain || gemm chain) --------
extern "C" void kernel_launch(void* const* d_in, const int* in_sizes, int n_in,
                              void* d_out, int out_size) {
    const float* x  = (const float*)d_in[0];
    const void*  ei = d_in[1];
    const float* W1 = (const float*)d_in[2];
    const float* b1 = (const float*)d_in[3];
    const float* Wl = (const float*)d_in[4];
    const float* bl = (const float*)d_in[5];
    const float* Wr = (const float*)d_in[6];
    const float* br = (const float*)d_in[7];
    const float* W3 = (const float*)d_in[8];
    const float* b3 = (const float*)d_in[9];
    float* out = (float*)d_out;

    static cudaStream_t s_edge = nullptr;
    static cudaEvent_t  ev_fork = nullptr, ev_join = nullptr;
    if (s_edge == nullptr) {
        cudaStreamCreateWithFlags(&s_edge, cudaStreamNonBlocking);
        cudaEventCreateWithFlags(&ev_fork, cudaEventDisableTiming);
        cudaEventCreateWithFlags(&ev_join, cudaEventDisableTiming);
    }

    cudaEventRecord(ev_fork, 0);
    cudaStreamWaitEvent(s_edge, ev_fork, 0);

    // chain B (edges) on s_edge
    k_zero_edge<<<(NN + 255) / 256, 256, 0, s_edge>>>((const int*)ei);
    k_deg<<<(EE + 255) / 256, 256, 0, s_edge>>>(ei);
    k_scan<<<1, 1024, 0, s_edge>>>();
    k_place<<<(EE + 255) / 256, 256, 0, s_edge>>>();
    cudaEventRecord(ev_join, s_edge);

    // chain A (gemm) on the capture-origin stream
    k_zero_xw<<<(NN * 32 + 255) / 256, 256>>>();
    dim3 ggrid(NN / BM, KSPLIT);
    k_gemm<<<ggrid, 64>>>(x, W1);

    // join, then the dependent tail
    cudaStreamWaitEvent(0, ev_join, 0);
    k_gcn<<<NN / 32, 256>>>(b1);
    k_sagehead<<<(NN * 32 + 255) / 256, 256>>>(Wl, bl, Wr, br, W3, b3, out);
}

// round 13
// speedup vs baseline: 1.1681x; 1.1681x over previous
#include <cuda_runtime.h>
#include <math.h>
#include <stdint.h>

#define NN 12288
#define EE 196608
#define FIN 1433

// ---------------- scratch (no allocations allowed) ----------------
__device__ __align__(16) float g_xw[NN * 32];    // x @ W1 (atomic accum)
__device__ __align__(16) float g_h[NN * 32];     // GCN output (post relu)
__device__ int   g_deg[NN];       // in-degree over col (excl self loop)
__device__ int   g_cnt[NN];       // out-degree over src
__device__ float g_dis[NN];       // (deg+1)^-1/2
__device__ int   g_is64;
__device__ int   g_src[EE];       // int32 edge cache
__device__ int   g_dst[EE];
__device__ int   g_rank[EE];      // edge's rank within its src bucket
__device__ int   g_ptr[NN + 1];   // CSR row pointers (by src)
__device__ int   g_csr[EE];       // CSR column (dst) list

__device__ __forceinline__ int edge_at(const void* ei, int j) {
    if (g_is64) return (int)((const long long*)ei)[j];
    return ((const int*)ei)[j];
}

// f32x2 packed FMA helpers
__device__ __forceinline__ void ffma2(unsigned long long& d,
                                      unsigned long long a,
                                      unsigned long long b) {
    asm("fma.rn.f32x2 %0, %1, %2, %0;" : "+l"(d) : "l"(a), "l"(b));
}
__device__ __forceinline__ unsigned long long dup2(float v) {
    unsigned long long r;
    asm("mov.b64 %0, {%1, %1};" : "=l"(r) : "f"(v));
    return r;
}
__device__ __forceinline__ float2 unpack2(unsigned long long v) {
    float2 r;
    asm("mov.b64 {%0, %1}, %2;" : "=f"(r.x), "=f"(r.y) : "l"(v));
    return r;
}
// cp.async 4B with zero-fill when pred is false
__device__ __forceinline__ void cp4(uint32_t dst_smem, const float* src, bool pred) {
    int sz = pred ? 4 : 0;
    asm volatile("cp.async.ca.shared.global [%0], [%1], 4, %2;"
                 :: "r"(dst_smem), "l"(src), "r"(sz));
}

// ---------------- K0: zero everything + dtype detect (pre-fork) ------------
__global__ void k_zero(const int* __restrict__ ei32) {
    int t = blockIdx.x * blockDim.x + threadIdx.x;
    if (t < NN * 32) g_xw[t] = 0.f;
    if (t < NN) { g_deg[t] = 0; g_cnt[t] = 0; }
    if (t == 0) {
        int all_zero_high = 1;
        for (int i = 0; i < 64; i++)
            if (ei32[2 * i + 1] != 0) { all_zero_high = 0; break; }
        g_is64 = all_zero_high;
    }
}

// ---------------- K1: degrees + edge cache + src-bucket rank ----------------
__global__ void k_deg(const void* __restrict__ ei) {
    int e = blockIdx.x * blockDim.x + threadIdx.x;
    if (e >= EE) return;
    int s = edge_at(ei, e);
    int c = edge_at(ei, EE + e);
    g_src[e] = s;
    g_dst[e] = c;
    atomicAdd(&g_deg[c], 1);
    g_rank[e] = atomicAdd(&g_cnt[s], 1);
}

// ---------------- K2: block scan of cnt -> ptr, plus dis ----------------
__global__ __launch_bounds__(1024) void k_scan() {
    __shared__ int warp_tot[32];
    int tid = threadIdx.x;
    int lane = tid & 31, wid = tid >> 5;
    int base = tid * 12;
    int loc[12];
    int s = 0;
#pragma unroll
    for (int i = 0; i < 12; i++) { loc[i] = g_cnt[base + i]; s += loc[i]; }
    int t = s;
#pragma unroll
    for (int off = 1; off < 32; off <<= 1) {
        int v = __shfl_up_sync(0xffffffffu, t, off);
        if (lane >= off) t += v;
    }
    if (lane == 31) warp_tot[wid] = t;
    __syncthreads();
    if (wid == 0) {
        int v = warp_tot[lane];
        int tv = v;
#pragma unroll
        for (int off = 1; off < 32; off <<= 1) {
            int u = __shfl_up_sync(0xffffffffu, tv, off);
            if (lane >= off) tv += u;
        }
        warp_tot[lane] = tv - v;  // exclusive warp base
    }
    __syncthreads();
    int run = warp_tot[wid] + (t - s);
#pragma unroll
    for (int i = 0; i < 12; i++) {
        g_ptr[base + i] = run;
        run += loc[i];
    }
    if (tid == 1023) g_ptr[NN] = run;
    for (int i = tid; i < NN; i += 1024)
        g_dis[i] = 1.0f / sqrtf((float)(g_deg[i] + 1));
}

// ---------------- K3: CSR placement (no atomics) ----------------
__global__ void k_place() {
    int e = blockIdx.x * blockDim.x + threadIdx.x;
    if (e >= EE) return;
    int s = g_src[e];
    g_csr[g_ptr[s] + g_rank[e]] = g_dst[e];
}

// ---------------- K4: xw += x @ W1, f32x2 FMA, cp.async TRIPLE buffer ------
#define BM 32
#define BK 32
#define KSPLIT 3
#define TPS 15
__global__ __launch_bounds__(64) void k_gemm(const float* __restrict__ x,
                                             const float* __restrict__ W1) {
    __shared__ float xs[3][BK][BM + 4];
    __shared__ float ws[3][BK][32];
    const int tid = threadIdx.x;
    const int tx = tid & 7;
    const int ty = tid >> 3;
    const int row0 = blockIdx.x * BM;
    const int lk = tid & 31;
    const int lr = tid >> 5;
    const int t0 = blockIdx.y * TPS;
    const int t1 = t0 + TPS;

    unsigned long long acc[4][2];
#pragma unroll
    for (int r = 0; r < 4; r++)
#pragma unroll
        for (int c = 0; c < 2; c++) acc[r][c] = 0ULL;

    auto copy_tile = [&](int t, int b) {
        int k0 = t * BK;
        int k = k0 + lk;
        bool kin = (k < FIN);
        const float* xp = kin ? &x[(row0 + lr) * FIN + k] : x;
#pragma unroll
        for (int i = 0; i < 16; i++) {
            int r = lr + i * 2;
            uint32_t dst = (uint32_t)__cvta_generic_to_shared(&xs[b][lk][r]);
            cp4(dst, kin ? &x[(row0 + r) * FIN + k] : xp, kin);
        }
#pragma unroll
        for (int i = 0; i < 16; i++) {
            int idx = tid + i * 64;
            int kk = idx >> 5, c = idx & 31;
            bool win = (k0 + kk) < FIN;
            uint32_t dst = (uint32_t)__cvta_generic_to_shared(&ws[b][kk][c]);
            cp4(dst, win ? &W1[(k0 + kk) * 32 + c] : W1, win);
        }
        asm volatile("cp.async.commit_group;" ::: "memory");
    };

    // prime two stages
    copy_tile(t0, 0);
    copy_tile(t0 + 1, 1);
    int b = 0;
    for (int t = t0; t < t1; t++) {
        if (t + 2 < t1) {
            copy_tile(t + 2, (b + 2) % 3);
            asm volatile("cp.async.wait_group 2;" ::: "memory");
        } else if (t + 1 < t1) {
            asm volatile("cp.async.wait_group 1;" ::: "memory");
        } else {
            asm volatile("cp.async.wait_group 0;" ::: "memory");
        }
        __syncthreads();
#pragma unroll
        for (int kk = 0; kk < BK; kk++) {
            float4 a = *reinterpret_cast<const float4*>(&xs[b][kk][ty * 4]);
            ulonglong2 bb = *reinterpret_cast<const ulonglong2*>(&ws[b][kk][tx * 4]);
            unsigned long long a0 = dup2(a.x), a1 = dup2(a.y);
            unsigned long long a2 = dup2(a.z), a3 = dup2(a.w);
            ffma2(acc[0][0], a0, bb.x); ffma2(acc[0][1], a0, bb.y);
            ffma2(acc[1][0], a1, bb.x); ffma2(acc[1][1], a1, bb.y);
            ffma2(acc[2][0], a2, bb.x); ffma2(acc[2][1], a2, bb.y);
            ffma2(acc[3][0], a3, bb.x); ffma2(acc[3][1], a3, bb.y);
        }
        __syncthreads();
        b = (b + 1) % 3;
    }
#pragma unroll
    for (int r = 0; r < 4; r++) {
        float2 lo = unpack2(acc[r][0]);
        float2 hi = unpack2(acc[r][1]);
        float* dst = &g_xw[(row0 + ty * 4 + r) * 32 + tx * 4];
        atomicAdd(dst + 0, lo.x);
        atomicAdd(dst + 1, lo.y);
        atomicAdd(dst + 2, hi.x);
        atomicAdd(dst + 3, hi.y);
    }
}

// ---------------- K5: GCN gather + self loop + bias + relu -> h -------------
// One warp per node; lane = feature. (proven 81.7us variant)
__global__ __launch_bounds__(256) void k_gcn(const float* __restrict__ b1) {
    int warp = (blockIdx.x * 256 + threadIdx.x) >> 5;
    int lane = threadIdx.x & 31;
    if (warp >= NN) return;
    int i = warp;
    int p0 = g_ptr[i], p1 = g_ptr[i + 1];
    float acc = 0.f;
    int j = p0;
    for (; j + 4 <= p1; j += 4) {
        int c0 = g_csr[j], c1 = g_csr[j + 1];
        int c2 = g_csr[j + 2], c3 = g_csr[j + 3];
        float w0 = g_dis[c0], w1 = g_dis[c1];
        float w2 = g_dis[c2], w3 = g_dis[c3];
        float v0 = g_xw[c0 * 32 + lane], v1 = g_xw[c1 * 32 + lane];
        float v2 = g_xw[c2 * 32 + lane], v3 = g_xw[c3 * 32 + lane];
        acc = fmaf(w0, v0, acc); acc = fmaf(w1, v1, acc);
        acc = fmaf(w2, v2, acc); acc = fmaf(w3, v3, acc);
    }
    for (; j < p1; j++) {
        int c = g_csr[j];
        acc = fmaf(g_dis[c], g_xw[c * 32 + lane], acc);
    }
    float di = g_dis[i];
    float v = di * acc + di * di * g_xw[i * 32 + lane] + b1[lane];
    g_h[i * 32 + lane] = fmaxf(v, 0.f);
}

// ---------------- K6: SAGE gather + normalize + head (fused) ---------------
__global__ __launch_bounds__(256) void k_sagehead(const float* __restrict__ Wl,
                                                  const float* __restrict__ bl,
                                                  const float* __restrict__ Wr,
                                                  const float* __restrict__ br,
                                                  const float* __restrict__ W3,
                                                  const float* __restrict__ b3,
                                                  float* __restrict__ out) {
    __shared__ float sWl[512], sWr[512], sW3[112], sbl[16], sbr[16], sb3[7];
    int tid = threadIdx.x;
    for (int i = tid; i < 512; i += 256) { sWl[i] = Wl[i]; sWr[i] = Wr[i]; }
    if (tid < 112) sW3[tid] = W3[tid];
    if (tid < 16) { sbl[tid] = bl[tid]; sbr[tid] = br[tid]; }
    if (tid < 7)  sb3[tid] = b3[tid];
    __syncthreads();

    const unsigned FULL = 0xffffffffu;
    int warp = (blockIdx.x * 256 + tid) >> 5;
    int lane = tid & 31;
    if (warp >= NN) return;
    int node = warp;

    int p0 = g_ptr[node], p1 = g_ptr[node + 1];
    float s = 0.f;
    int j = p0;
    for (; j + 4 <= p1; j += 4) {
        int c0 = g_csr[j], c1 = g_csr[j + 1];
        int c2 = g_csr[j + 2], c3 = g_csr[j + 3];
        s += g_h[c0 * 32 + lane] + g_h[c1 * 32 + lane]
           + g_h[c2 * 32 + lane] + g_h[c3 * 32 + lane];
    }
    for (; j < p1; j++) s += g_h[g_csr[j] * 32 + lane];
    int cnt = p1 - p0;
    float ak = (cnt > 0) ? s / (float)cnt : 0.f;
    float hk = g_h[node * 32 + lane];

    int l16 = lane & 15;
    float acc = 0.f;
#pragma unroll
    for (int k = 0; k < 32; k++) {
        float hv = __shfl_sync(FULL, hk, k);
        float av = __shfl_sync(FULL, ak, k);
        acc = fmaf(hv, sWl[k * 16 + l16], acc);
        acc = fmaf(av, sWr[k * 16 + l16], acc);
    }
    float o = fmaxf(acc + sbl[l16] + sbr[l16], 0.f);
    if (lane >= 16) o = 0.f;

    float ss = o * o;
#pragma unroll
    for (int off = 16; off; off >>= 1) ss += __shfl_xor_sync(FULL, ss, off);
    float on = o / (sqrtf(ss) + 1e-6f);

    int c7 = lane < 7 ? lane : 6;
    float lg = 0.f;
#pragma unroll
    for (int k = 0; k < 16; k++) {
        float ov = __shfl_sync(FULL, on, k);
        lg = fmaf(ov, sW3[k * 7 + c7], lg);
    }
    lg += sb3[c7];

    float v = lane < 7 ? lg : -INFINITY;
    float m = v;
#pragma unroll
    for (int off = 4; off; off >>= 1) m = fmaxf(m, __shfl_xor_sync(FULL, m, off));
    float ex = lane < 7 ? expf(lg - m) : 0.f;
    float sm = ex;
#pragma unroll
    for (int off = 4; off; off >>= 1) sm += __shfl_xor_sync(FULL, sm, off);
    if (lane < 7) out[node * 7 + lane] = ex / sm;
}

// ---------------- launch (forked capture: edge chain || gemm chain) --------
extern "C" void kernel_launch(void* const* d_in, const int* in_sizes, int n_in,
                              void* d_out, int out_size) {
    const float* x  = (const float*)d_in[0];
    const void*  ei = d_in[1];
    const float* W1 = (const float*)d_in[2];
    const float* b1 = (const float*)d_in[3];
    const float* Wl = (const float*)d_in[4];
    const float* bl = (const float*)d_in[5];
    const float* Wr = (const float*)d_in[6];
    const float* br = (const float*)d_in[7];
    const float* W3 = (const float*)d_in[8];
    const float* b3 = (const float*)d_in[9];
    float* out = (float*)d_out;

    static cudaStream_t s_edge = nullptr;
    static cudaEvent_t  ev_fork = nullptr, ev_join = nullptr;
    if (s_edge == nullptr) {
        cudaStreamCreateWithFlags(&s_edge, cudaStreamNonBlocking);
        cudaEventCreateWithFlags(&ev_fork, cudaEventDisableTiming);
        cudaEventCreateWithFlags(&ev_join, cudaEventDisableTiming);
    }

    // zero everything first (both chains depend on it)
    k_zero<<<(NN * 32 + 255) / 256, 256>>>((const int*)ei);

    // fork: edge-preprocessing chain runs concurrently with the GEMM chain
    cudaEventRecord(ev_fork, 0);
    cudaStreamWaitEvent(s_edge, ev_fork, 0);

    // chain B (edges) on s_edge
    k_deg<<<(EE + 255) / 256, 256, 0, s_edge>>>(ei);
    k_scan<<<1, 1024, 0, s_edge>>>();
    k_place<<<(EE + 255) / 256, 256, 0, s_edge>>>();
    cudaEventRecord(ev_join, s_edge);

    // chain A (gemm) on the capture-origin stream
    dim3 ggrid(NN / BM, KSPLIT);
    k_gemm<<<ggrid, 64>>>(x, W1);

    // join, then the dependent tail
    cudaStreamWaitEvent(0, ev_join, 0);
    k_gcn<<<(NN * 32 + 255) / 256, 256>>>(b1);
    k_sagehead<<<(NN * 32 + 255) / 256, 256>>>(Wl, bl, Wr, br, W3, b3, out);
}